// round 9
// baseline (speedup 1.0000x reference)
#include <cuda_runtime.h>
#include <cuda_bf16.h>

// Sparsemax over last dim, rows of N=1024 fp32.
// Persistent warps, one row per warp per step, double-buffered register
// pipeline: next row's 8 LDG.128 issue before current row's compute/store,
// so every warp has loads in flight ~continuously (DRAM stays busy without
// needing high occupancy).
// tau: scan-compaction of candidates {x > max-1} + exact closed-form rank test.

static constexpr int N = 1024;
static constexpr int THREADS = 256;            // 8 warps per CTA
static constexpr int WARPS = THREADS / 32;
static constexpr int CAP = 128;                // candidate buffer per warp
static constexpr int GRID = 296;               // 148 SMs x 2 CTAs: one wave

__device__ __forceinline__ void load_row(float4 (&d)[8], const float4* __restrict__ p, int lane) {
    #pragma unroll
    for (int i = 0; i < 8; ++i) d[i] = p[lane + 32 * i];
}

__device__ __forceinline__ void process_row(const float4 (&d)[8],
                                            float4* __restrict__ orw,
                                            int lane, float* __restrict__ cand) {
    // ---- warp max ----
    float m = -3.402823466e38f;
    #pragma unroll
    for (int i = 0; i < 8; ++i)
        m = fmaxf(m, fmaxf(fmaxf(d[i].x, d[i].y), fmaxf(d[i].z, d[i].w)));
    #pragma unroll
    for (int o = 16; o > 0; o >>= 1)
        m = fmaxf(m, __shfl_xor_sync(0xFFFFFFFFu, m, o));

    // tau in [-1, 0): support subset of {x > m - 1}
    const float thr = m - 1.0f;

    // ---- per-thread candidate count ----
    unsigned cnt = 0;
    #pragma unroll
    for (int i = 0; i < 8; ++i) {
        cnt += (d[i].x > thr);
        cnt += (d[i].y > thr);
        cnt += (d[i].z > thr);
        cnt += (d[i].w > thr);
    }

    // ---- warp exclusive scan (lane-major candidate order) ----
    unsigned incl = cnt;
    #pragma unroll
    for (int o = 1; o < 32; o <<= 1) {
        unsigned t = __shfl_up_sync(0xFFFFFFFFu, incl, o);
        if (lane >= o) incl += t;
    }
    const int c = (int)__shfl_sync(0xFFFFFFFFu, incl, 31);
    int idx = (int)(incl - cnt);

    // ---- write candidates (z = x - m) at scanned offsets ----
    if (c <= CAP) {
        #pragma unroll
        for (int i = 0; i < 8; ++i) {
            const float vv[4] = { d[i].x, d[i].y, d[i].z, d[i].w };
            #pragma unroll
            for (int j = 0; j < 4; ++j)
                if (vv[j] > thr) cand[idx++] = vv[j] - m;
        }
    }
    __syncwarp();

    float tau;
    if (c <= CAP) {
        // rank r and prefix-ordered sum S over (value desc, slot asc).
        // k = max rank with 1 + r*v > S; tau = (sum is_gt*v - 1)/k.
        unsigned kmax = 0u;
        float num = 0.0f;
        for (int slot = lane; slot < c; slot += 32) {
            const float v = cand[slot];
            float S = 0.0f, r = 0.0f;
            for (int j = 0; j < c; ++j) {
                const float u = cand[j];
                bool ge = (u > v) || (u == v && j <= slot);
                if (ge) { S += u; r += 1.0f; }
            }
            if (1.0f + r * v > S) {
                if ((unsigned)r > kmax) kmax = (unsigned)r;
                num += v;
            }
        }
        kmax = __reduce_max_sync(0xFFFFFFFFu, kmax);
        #pragma unroll
        for (int o = 16; o > 0; o >>= 1)
            num += __shfl_xor_sync(0xFFFFFFFFu, num, o);
        tau = (num - 1.0f) / (float)kmax;
    } else {
        // ---- fallback (essentially never taken): warp-local Michelot ----
        float s = 0.0f;
        #pragma unroll
        for (int i = 0; i < 8; ++i)
            s += ((d[i].x - m) + (d[i].y - m)) + ((d[i].z - m) + (d[i].w - m));
        #pragma unroll
        for (int o = 16; o > 0; o >>= 1)
            s += __shfl_xor_sync(0xFFFFFFFFu, s, o);
        tau = (s - 1.0f) / (float)N;
        float prev_k = (float)N;
        #pragma unroll 1
        for (int it = 0; it < 64; ++it) {
            float ps = 0.0f, pk = 0.0f;
            #pragma unroll
            for (int i = 0; i < 8; ++i) {
                const float vv[4] = { d[i].x - m, d[i].y - m, d[i].z - m, d[i].w - m };
                #pragma unroll
                for (int j = 0; j < 4; ++j)
                    if (vv[j] > tau) { ps += vv[j]; pk += 1.0f; }
            }
            #pragma unroll
            for (int o = 16; o > 0; o >>= 1) {
                ps += __shfl_xor_sync(0xFFFFFFFFu, ps, o);
                pk += __shfl_xor_sync(0xFFFFFFFFu, pk, o);
            }
            float k = (pk > 0.0f) ? pk : 1.0f;
            float nt = (ps - 1.0f) / k;
            bool done = (nt == tau) && (k == prev_k);
            tau = nt;
            prev_k = k;
            if (done) break;
        }
    }

    // ---- output: max(x - (m + tau), 0) ----
    const float t2 = m + tau;
    #pragma unroll
    for (int i = 0; i < 8; ++i) {
        float4 o;
        o.x = fmaxf(d[i].x - t2, 0.0f);
        o.y = fmaxf(d[i].y - t2, 0.0f);
        o.z = fmaxf(d[i].z - t2, 0.0f);
        o.w = fmaxf(d[i].w - t2, 0.0f);
        orw[lane + 32 * i] = o;
    }
}

__global__ __launch_bounds__(THREADS, 2)
void sparsemax_kernel(const float* __restrict__ x, float* __restrict__ out, int rows) {
    __shared__ float cand[WARPS][CAP];

    const int lane = threadIdx.x & 31;
    const int w    = threadIdx.x >> 5;
    float* my_cand = cand[w];

    const int g = blockIdx.x * WARPS + w;        // global warp id
    const int G = gridDim.x * WARPS;             // total warps (stride)

    float4 A[8], B[8];

    int row = g;
    if (row >= rows) return;
    load_row(A, reinterpret_cast<const float4*>(x + (size_t)row * N), lane);

    #pragma unroll 1
    while (true) {
        const int n1 = row + G;
        if (n1 < rows)
            load_row(B, reinterpret_cast<const float4*>(x + (size_t)n1 * N), lane);

        process_row(A, reinterpret_cast<float4*>(out + (size_t)row * N), lane, my_cand);

        if (n1 >= rows) break;

        const int n2 = n1 + G;
        if (n2 < rows)
            load_row(A, reinterpret_cast<const float4*>(x + (size_t)n2 * N), lane);

        process_row(B, reinterpret_cast<float4*>(out + (size_t)n1 * N), lane, my_cand);

        if (n2 >= rows) break;
        row = n2;
    }
}

extern "C" void kernel_launch(void* const* d_in, const int* in_sizes, int n_in,
                              void* d_out, int out_size) {
    const float* x = (const float*)d_in[0];
    float* out = (float*)d_out;
    int rows = in_sizes[0] / N;
    sparsemax_kernel<<<GRID, THREADS>>>(x, out, rows);
}